// round 7
// baseline (speedup 1.0000x reference)
#include <cuda_runtime.h>
#include <math.h>
#include <cstdint>

// Problem constants (fixed by the reference)
#define NE 16
#define NW 3
#define NB 64
#define NP 4096
#define BP (NB * NP)
#define HBP (BP / 2)       // 131072 float2 per (expert,proj) plane
#define HP (NP / 2)        // 2048
#define TILE 128           // float2 slots per tile
#define NTILES (HBP / TILE) // 1024
#define NPLANE 96          // 32 Q + 32 K + 32 V planes
#define PLANE_TILE_BYTES (TILE * 8)              // 1024 B
#define STAGE_BYTES (NPLANE * PLANE_TILE_BYTES)  // 98304 B
#define NSTAGE 2
#define SMEM_BYTES (NSTAGE * STAGE_BYTES)        // 196608 B
#define GRID 148
#define THREADS 512

__global__ void __launch_bounds__(THREADS, 1)
cantor_attn_kernel(const float2* __restrict__ Qp,
                   const float2* __restrict__ Kp,
                   const float2* __restrict__ Vp,
                   const float*  __restrict__ betas,
                   const float*  __restrict__ temperature,
                   const int*    __restrict__ routes,
                   float2*       __restrict__ out)
{
    extern __shared__ float2 sm[];     // [NSTAGE][NPLANE][TILE]
    __shared__ uint64_t mbar[NSTAGE];
    __shared__ int   s_route[NE * NW];
    __shared__ float s_gate[NE * NW];
    __shared__ float s_inv;

    const int t = threadIdx.x;
    const uint32_t mb0 = (uint32_t)__cvta_generic_to_shared(&mbar[0]);
    const uint32_t mb1 = (uint32_t)__cvta_generic_to_shared(&mbar[1]);

    if (t == 0) {
        asm volatile("mbarrier.init.shared.b64 [%0], 1;" :: "r"(mb0) : "memory");
        asm volatile("mbarrier.init.shared.b64 [%0], 1;" :: "r"(mb1) : "memory");
    }
    if (t < NE * NW) {
        const int e = t / NW;
        const int r = routes[t];
        s_route[t] = r;
        s_gate[t]  = (r != e) ? __fdividef(1.0f, 1.0f + __expf(-betas[t])) : 1.0f;
    }
    if (t == NE * NW) {
        s_inv = __fdividef(1.0f, sqrtf(128.0f) * fabsf(temperature[0]));
    }
    __syncthreads();

    const int bid = blockIdx.x;
    // tiles: bid, bid+GRID, ... < NTILES
    const int niter = (NTILES - 1 - bid) / GRID + 1;

    // thread-0 helper: expect_tx + 96 bulk copies for one tile into one stage
    auto issue_tile = [&](int tile, int stage) {
        const uint32_t mb = stage ? mb1 : mb0;
        asm volatile("mbarrier.arrive.expect_tx.shared.b64 _, [%0], %1;"
                     :: "r"(mb), "r"((uint32_t)STAGE_BYTES) : "memory");
        const long tb = (long)tile * TILE;
        uint32_t dst = (uint32_t)__cvta_generic_to_shared(sm + (long)stage * NPLANE * TILE);
        #pragma unroll 1
        for (int pl = 0; pl < 32; pl++) {
            const float2* sq = Qp + (long)pl * HBP + tb;
            const float2* sk = Kp + (long)pl * HBP + tb;
            const float2* sv = Vp + (long)pl * HBP + tb;
            const uint32_t dq = dst + pl * PLANE_TILE_BYTES;
            const uint32_t dk = dst + (32 + pl) * PLANE_TILE_BYTES;
            const uint32_t dv = dst + (64 + pl) * PLANE_TILE_BYTES;
            asm volatile("cp.async.bulk.shared::cta.global.mbarrier::complete_tx::bytes [%0], [%1], %2, [%3];"
                         :: "r"(dq), "l"(sq), "r"((uint32_t)PLANE_TILE_BYTES), "r"(mb) : "memory");
            asm volatile("cp.async.bulk.shared::cta.global.mbarrier::complete_tx::bytes [%0], [%1], %2, [%3];"
                         :: "r"(dk), "l"(sk), "r"((uint32_t)PLANE_TILE_BYTES), "r"(mb) : "memory");
            asm volatile("cp.async.bulk.shared::cta.global.mbarrier::complete_tx::bytes [%0], [%1], %2, [%3];"
                         :: "r"(dv), "l"(sv), "r"((uint32_t)PLANE_TILE_BYTES), "r"(mb) : "memory");
        }
    };

    // prologue: fill stage 0 with first tile
    if (t == 0) issue_tile(bid, 0);

    const int s    = t & (TILE - 1);     // slot
    const int q    = t >> 7;             // expert quarter (0..3)
    const float inv = s_inv;

    for (int i = 0; i < niter; i++) {
        const int stage = i & 1;
        const int tile  = bid + i * GRID;
        const int next  = tile + GRID;

        // issue next tile into the other stage (its compute finished last iter;
        // __syncthreads at loop end guarantees no reader remains)
        if (t == 0 && next < NTILES) issue_tile(next, stage ^ 1);

        // wait current stage full; parity = (i>>1)&1
        {
            const uint32_t mb = stage ? mb1 : mb0;
            const uint32_t ph = (i >> 1) & 1;
            uint32_t done;
            asm volatile(
                "{\n\t.reg .pred p;\n\t"
                "mbarrier.try_wait.parity.acquire.cta.shared::cta.b64 p, [%1], %2;\n\t"
                "selp.b32 %0, 1, 0, p;\n\t}"
                : "=r"(done) : "r"(mb), "r"(ph) : "memory");
            if (!done) {
                asm volatile(
                    "{\n\t.reg .pred P1;\n\t"
                    "WAIT_LOOP_%=:\n\t"
                    "mbarrier.try_wait.parity.acquire.cta.shared::cta.b64 P1, [%0], %1, 0x989680;\n\t"
                    "@P1 bra.uni WAIT_DONE_%=;\n\t"
                    "bra.uni WAIT_LOOP_%=;\n\t"
                    "WAIT_DONE_%=:\n\t}"
                    :: "r"(mb), "r"(ph) : "memory");
            }
        }

        const float2* __restrict__ S = sm + (long)stage * NPLANE * TILE;
        const int idx2 = tile * TILE + s;
        const int b    = idx2 >> 11;          // / HP
        const int p2   = idx2 & (HP - 1);
        const long obase = (long)b * (NE * HP) + p2;

        #pragma unroll
        for (int k = 0; k < 4; k++) {
            const int e  = q * 4 + k;
            const int r0 = s_route[e * NW + 0];
            const int r1 = s_route[e * NW + 1];
            const int r2 = s_route[e * NW + 2];
            const float g0 = s_gate[e * NW + 0];
            const float g1 = s_gate[e * NW + 1];
            const float g2 = s_gate[e * NW + 2];

            const float2 qa  = S[(2 * e)     * TILE + s];
            const float2 qb  = S[(2 * e + 1) * TILE + s];
            const float2 k0a = S[(32 + 2 * r0)     * TILE + s];
            const float2 k0b = S[(32 + 2 * r0 + 1) * TILE + s];
            const float2 k1a = S[(32 + 2 * r1)     * TILE + s];
            const float2 k1b = S[(32 + 2 * r1 + 1) * TILE + s];
            const float2 k2a = S[(32 + 2 * r2)     * TILE + s];
            const float2 k2b = S[(32 + 2 * r2 + 1) * TILE + s];
            const float2 v0a = S[(64 + 2 * r0)     * TILE + s];
            const float2 v0b = S[(64 + 2 * r0 + 1) * TILE + s];
            const float2 v1a = S[(64 + 2 * r1)     * TILE + s];
            const float2 v1b = S[(64 + 2 * r1 + 1) * TILE + s];
            const float2 v2a = S[(64 + 2 * r2)     * TILE + s];
            const float2 v2b = S[(64 + 2 * r2 + 1) * TILE + s];

            float2 res;

#define DO_LANE(c)                                                         \
            {                                                              \
                const float qm = 0.5f * (qa.c + qb.c);                     \
                const float k0 = 0.5f * (k0a.c + k0b.c);                   \
                const float k1 = 0.5f * (k1a.c + k1b.c);                   \
                const float k2 = 0.5f * (k2a.c + k2b.c);                   \
                const float v0 = 0.5f * (v0a.c + v0b.c);                   \
                const float v1 = 0.5f * (v1a.c + v1b.c);                   \
                const float v2 = 0.5f * (v2a.c + v2b.c);                   \
                const float qi = qm * inv;                                 \
                const float s0 = qi * k0 * g0;                             \
                const float s1 = qi * k1 * g1;                             \
                const float s2 = qi * k2 * g2;                             \
                const float m  = fmaxf(fmaxf(s0, s1), s2);                 \
                const float x0 = __expf(s0 - m);                           \
                const float x1 = __expf(s1 - m);                           \
                const float x2 = __expf(s2 - m);                           \
                const float rs = __fdividef(1.0f, x0 + x1 + x2);           \
                res.c = (x0 * v0 + x1 * v1 + x2 * v2) * rs;                \
            }

            DO_LANE(x)
            DO_LANE(y)
#undef DO_LANE

            out[obase + (long)e * HP] = res;
        }

        __syncthreads();   // all readers done before this stage is refilled
    }
}

extern "C" void kernel_launch(void* const* d_in, const int* in_sizes, int n_in,
                              void* d_out, int out_size)
{
    // metadata order: Q_proj, K_proj, V_proj, betas, temperature, routes, num_patches
    const float2* Qp    = (const float2*)d_in[0];
    const float2* Kp    = (const float2*)d_in[1];
    const float2* Vp    = (const float2*)d_in[2];
    const float*  betas = (const float*)d_in[3];
    const float*  temp  = (const float*)d_in[4];
    const int*    routes= (const int*)d_in[5];
    float2*       out   = (float2*)d_out;

    (void)in_sizes; (void)n_in; (void)out_size;

    static bool attr_set = false;
    if (!attr_set) {
        cudaFuncSetAttribute(cantor_attn_kernel,
                             cudaFuncAttributeMaxDynamicSharedMemorySize, SMEM_BYTES);
        attr_set = true;
    }

    cantor_attn_kernel<<<GRID, THREADS, SMEM_BYTES>>>(Qp, Kp, Vp, betas, temp, routes, out);
}

// round 8
// speedup vs baseline: 1.2129x; 1.2129x over previous
#include <cuda_runtime.h>
#include <math.h>
#include <cstdint>

// Problem constants (fixed by the reference)
#define NE 16
#define NW 3
#define NB 64
#define NP 4096
#define BP (NB * NP)
#define HBP (BP / 2)        // 131072 float2 per (expert,proj) plane
#define HP (NP / 2)         // 2048
#define TILE 128            // float2 slots per tile
#define NTILES (HBP / TILE) // 1024
#define KVPL 64             // 32 K-planes + 32 V-planes staged via bulk copy
#define CHUNK (TILE * 8)    // 1024 B per plane chunk
#define STAGE_B (KVPL * CHUNK)   // 65536 B per stage
#define NSTAGE 3
#define SMEM_BYTES (NSTAGE * STAGE_B)  // 196608 B
#define GRID 148
#define THREADS 512

__global__ void __launch_bounds__(THREADS, 1)
cantor_attn_kernel(const float2* __restrict__ Qp,
                   const float2* __restrict__ Kp,
                   const float2* __restrict__ Vp,
                   const float*  __restrict__ betas,
                   const float*  __restrict__ temperature,
                   const int*    __restrict__ routes,
                   float2*       __restrict__ out)
{
    extern __shared__ float2 sm[];            // [NSTAGE][KVPL][TILE]
    __shared__ uint64_t mbar[NSTAGE];
    __shared__ int   s_route[NE * NW];
    __shared__ float s_gate[NE * NW];         // gate * inv * 0.25 (pre-folded)

    const int t = threadIdx.x;
    const uint32_t mb_base  = (uint32_t)__cvta_generic_to_shared(&mbar[0]);
    const uint32_t sm_base  = (uint32_t)__cvta_generic_to_shared(sm);

    if (t < NSTAGE) {
        asm volatile("mbarrier.init.shared.b64 [%0], %1;"
                     :: "r"(mb_base + t * 8), "r"((uint32_t)KVPL) : "memory");
    }
    if (t < NE * NW) {
        const int e = t / NW;
        const int r = routes[t];
        s_route[t] = r;
        const float inv  = __fdividef(1.0f, sqrtf(128.0f) * fabsf(temperature[0]));
        const float gate = (r != e) ? __fdividef(1.0f, 1.0f + __expf(-betas[t])) : 1.0f;
        s_gate[t] = gate * inv * 0.25f;
    }
    __syncthreads();

    const int bid   = blockIdx.x;
    const int niter = (NTILES - 1 - bid) / GRID + 1;   // >= 6 for all bids

    // Per-thread copy issue: threads 0..63 each own one K/V plane chunk.
    // Each issues its own arrive.expect_tx THEN its own copy -> arrival count
    // reaches 64 only after all expects are registered; phase flips only when
    // all 65536 bytes have landed. No cross-thread ordering needed.
    const float2* mysrc_base = (t < 32) ? (Kp + (long)t * HBP)
                                        : (Vp + (long)(t - 32) * HBP);
    const uint32_t mydst_off = sm_base + (uint32_t)t * CHUNK;

    auto issue = [&](int tile, int stage) {
        const uint32_t mb = mb_base + stage * 8;
        asm volatile("mbarrier.arrive.expect_tx.shared.b64 _, [%0], %1;"
                     :: "r"(mb), "r"((uint32_t)CHUNK) : "memory");
        const float2*  src = mysrc_base + (long)tile * TILE;
        const uint32_t dst = mydst_off + (uint32_t)stage * STAGE_B;
        asm volatile(
            "cp.async.bulk.shared::cta.global.mbarrier::complete_tx::bytes [%0], [%1], %2, [%3];"
            :: "r"(dst), "l"(src), "r"((uint32_t)CHUNK), "r"(mb) : "memory");
    };

    // Prologue: fill stages 0 and 1 (tiles bid, bid+GRID always < NTILES)
    if (t < KVPL) {
        issue(bid, 0);
        issue(bid + GRID, 1);
    }

    const int s   = t & (TILE - 1);   // slot within tile
    const int qrt = t >> 7;           // expert quarter (0..3)

    for (int i = 0; i < niter; i++) {
        const int tile  = bid + i * GRID;
        const int stage = i % 3;

        // Issue tile i+2 into stage (i+2)%3 — that stage was last read at
        // iteration i-1 and freed by the trailing __syncthreads.
        if (t < KVPL) {
            const int nt = tile + 2 * GRID;
            if (nt < NTILES) issue(nt, (i + 2) % 3);
        }

        // Prefetch Q for this tile via demand LDG (overlaps the TMA wait;
        // runs on the MSHR path concurrently with the bulk-copy engine).
        const int idx2 = tile * TILE + s;
        float2 qa[4], qb[4];
        #pragma unroll
        for (int k = 0; k < 4; k++) {
            const int e = qrt * 4 + k;
            qa[k] = Qp[(long)(e * 2)     * HBP + idx2];
            qb[k] = Qp[(long)(e * 2 + 1) * HBP + idx2];
        }

        // Wait current stage full; parity = (i/3)&1
        {
            const uint32_t mb = mb_base + stage * 8;
            const uint32_t ph = (uint32_t)((i / 3) & 1);
            uint32_t done;
            asm volatile(
                "{\n\t.reg .pred p;\n\t"
                "mbarrier.try_wait.parity.acquire.cta.shared::cta.b64 p, [%1], %2;\n\t"
                "selp.b32 %0, 1, 0, p;\n\t}"
                : "=r"(done) : "r"(mb), "r"(ph) : "memory");
            if (!done) {
                asm volatile(
                    "{\n\t.reg .pred P1;\n\t"
                    "WAIT_LOOP_%=:\n\t"
                    "mbarrier.try_wait.parity.acquire.cta.shared::cta.b64 P1, [%0], %1, 0x989680;\n\t"
                    "@P1 bra.uni WAIT_DONE_%=;\n\t"
                    "bra.uni WAIT_LOOP_%=;\n\t"
                    "WAIT_DONE_%=:\n\t}"
                    :: "r"(mb), "r"(ph) : "memory");
            }
        }

        const float2* __restrict__ S = sm + (long)stage * (KVPL * TILE);
        const int b  = idx2 >> 11;          // / HP
        const int p2 = idx2 & (HP - 1);
        const long obase = (long)b * (NE * HP) + p2;

        #pragma unroll
        for (int k = 0; k < 4; k++) {
            const int e  = qrt * 4 + k;
            const int r0 = s_route[e * NW + 0];
            const int r1 = s_route[e * NW + 1];
            const int r2 = s_route[e * NW + 2];
            const float g0 = s_gate[e * NW + 0];   // gate*inv*0.25
            const float g1 = s_gate[e * NW + 1];
            const float g2 = s_gate[e * NW + 2];

            // K planes at chunks [2r, 2r+1]; V planes at chunks [32+... ] -> 2r shifted by 32 planes = chunk 32+2r? No:
            // thread t<32 staged K plane t at chunk t; t in [32,64) staged V plane t-32 at chunk t.
            const float2 k0a = S[(2 * r0 == 0 ? 0 : 2 * r0) * 0 + 0]; // placeholder removed below
            (void)k0a;
            const float2 K0a = S[( (2 * r0 < 32) ? (2 * r0)     : 0 ) * 0 + (2 * r0)     * TILE / 2 * 0 + 0]; (void)K0a;
            // -- real indexing (K plane p at chunk p, V plane p at chunk 32+p) --
            const float2 ka0 = S[(2 * r0 + 0 < 32 ? 1 : 1) * 0 + 0]; (void)ka0;
            float2 res;
            {
                // K plane indices: 2*r and 2*r+1 are in [0,32) -> chunks 2r, 2r+1
                const float2 kA0 = S[(2 * r0)     * TILE + s];
                const float2 kB0 = S[(2 * r0 + 1) * TILE + s];
                const float2 kA1 = S[(2 * r1)     * TILE + s];
                const float2 kB1 = S[(2 * r1 + 1) * TILE + s];
                const float2 kA2 = S[(2 * r2)     * TILE + s];
                const float2 kB2 = S[(2 * r2 + 1) * TILE + s];
                const float2 vA0 = S[(32 + 2 * r0)     * TILE + s];
                const float2 vB0 = S[(32 + 2 * r0 + 1) * TILE + s];
                const float2 vA1 = S[(32 + 2 * r1)     * TILE + s];
                const float2 vB1 = S[(32 + 2 * r1 + 1) * TILE + s];
                const float2 vA2 = S[(32 + 2 * r2)     * TILE + s];
                const float2 vB2 = S[(32 + 2 * r2 + 1) * TILE + s];

#define DO_LANE(c)                                                          \
                {                                                           \
                    const float qt = qa[k].c + qb[k].c;                     \
                    const float s0 = qt * g0 * (kA0.c + kB0.c);             \
                    const float s1 = qt * g1 * (kA1.c + kB1.c);             \
                    const float s2 = qt * g2 * (kA2.c + kB2.c);             \
                    const float x0 = __expf(s0);                            \
                    const float x1 = __expf(s1);                            \
                    const float x2 = __expf(s2);                            \
                    const float rs = __fdividef(0.5f, x0 + x1 + x2);        \
                    const float nu = x0 * (vA0.c + vB0.c)                   \
                                   + x1 * (vA1.c + vB1.c)                   \
                                   + x2 * (vA2.c + vB2.c);                  \
                    res.c = nu * rs;                                        \
                }
                DO_LANE(x)
                DO_LANE(y)
#undef DO_LANE
            }

            out[obase + (long)e * HP] = res;
        }

        __syncthreads();   // all readers done before this stage is refilled
    }
}

extern "C" void kernel_launch(void* const* d_in, const int* in_sizes, int n_in,
                              void* d_out, int out_size)
{
    // metadata order: Q_proj, K_proj, V_proj, betas, temperature, routes, num_patches
    const float2* Qp    = (const float2*)d_in[0];
    const float2* Kp    = (const float2*)d_in[1];
    const float2* Vp    = (const float2*)d_in[2];
    const float*  betas = (const float*)d_in[3];
    const float*  temp  = (const float*)d_in[4];
    const int*    routes= (const int*)d_in[5];
    float2*       out   = (float2*)d_out;

    (void)in_sizes; (void)n_in; (void)out_size;

    static bool attr_set = false;
    if (!attr_set) {
        cudaFuncSetAttribute(cantor_attn_kernel,
                             cudaFuncAttributeMaxDynamicSharedMemorySize, SMEM_BYTES);
        attr_set = true;
    }

    cantor_attn_kernel<<<GRID, THREADS, SMEM_BYTES>>>(Qp, Kp, Vp, betas, temp, routes, out);
}